// round 16
// baseline (speedup 1.0000x reference)
#include <cuda_runtime.h>
#include <cuda_bf16.h>
#include <mma.h>
#include <cstdint>

using namespace nvcuda;

// Problem constants
static constexpr int NN = 50000;   // nodes
static constexpr int EE = 800000;  // edges
static constexpr int HH = 160;     // hidden
static constexpr float LEAK = 0.01f;

// ---------------- device scratch (allocation-free rule) ----------------
__device__ float g_t[NN * HH];          // encoder concat output
__device__ float g_hA[NN * HH];
__device__ float g_hB[NN * HH];
__device__ float g_mean[2 * NN * HH];   // per-relation aggregated means
__device__ int   g_deg[2 * NN];
__device__ int   g_off[2 * NN + 1];
__device__ int   g_cur[2 * NN];
__device__ int   g_elist[EE];
__device__ int   g_bsum[512];

// Weight split planes (bf16 hi / lo), precomputed once per replay.
static constexpr int OFF_NP    = 0;              // 6*32
static constexpr int OFF_NC    = 192;            // 11*32
static constexpr int OFF_DES   = 544;            // 768*32
static constexpr int OFF_TEXT  = 25120;
static constexpr int OFF_TW    = 49696;
static constexpr int OFF_IN    = 74272;          // 160*160
static constexpr int OFF_ROOT1 = 99872;
static constexpr int OFF_REL1A = 125472;
static constexpr int OFF_REL1B = 151072;
static constexpr int OFF_ROOT2 = 176672;
static constexpr int OFF_REL2A = 202272;
static constexpr int OFF_REL2B = 227872;
static constexpr int OFF_O1    = 253472;         // 160*80
static constexpr int W_TOTAL   = 266272;
__device__ __align__(16) __nv_bfloat16 g_wh[W_TOTAL];
__device__ __align__(16) __nv_bfloat16 g_wl[W_TOTAL];

// ---------------- weight split precompute ----------------
struct WSegs {
    const float* src[13];
    int len[13];
    int off[13];
};
__global__ void k_splitw(WSegs s) {
    int i = blockIdx.x * blockDim.x + threadIdx.x;
    #pragma unroll
    for (int seg = 0; seg < 13; seg++) {
        int l = s.len[seg];
        if (i < l) {
            float x = s.src[seg][i];
            __nv_bfloat16 hb = __float2bfloat16(x);
            g_wh[s.off[seg] + i] = hb;
            g_wl[s.off[seg] + i] = __float2bfloat16(x - __bfloat162float(hb));
            return;
        }
        i -= l;
    }
}

// ---------------- CSR build ----------------
__global__ void k_zero_deg() {
    int i = blockIdx.x * blockDim.x + threadIdx.x;
    if (i < 2 * NN) g_deg[i] = 0;
}

__global__ void k_count(const int* __restrict__ ei, const int* __restrict__ et) {
    int e = blockIdx.x * blockDim.x + threadIdx.x;
    if (e >= EE) return;
    int d = ei[EE + e];
    int r = et[e];
    atomicAdd(&g_deg[r * NN + d], 1);
}

// ---- decoupled 3-phase scan over 2N counts ----
__global__ void k_scan1() {
    __shared__ int wsum[8];
    const int TOT = 2 * NN;
    int i = blockIdx.x * 256 + threadIdx.x;
    int lane = threadIdx.x & 31;
    int wid = threadIdx.x >> 5;
    int v = (i < TOT) ? g_deg[i] : 0;
    int incl = v;
    #pragma unroll
    for (int o = 1; o < 32; o <<= 1) {
        int t = __shfl_up_sync(0xFFFFFFFFu, incl, o);
        if (lane >= o) incl += t;
    }
    if (lane == 31) wsum[wid] = incl;
    __syncthreads();
    if (wid == 0 && lane < 8) {
        int s = wsum[lane];
        int si = s;
        #pragma unroll
        for (int o = 1; o < 8; o <<= 1) {
            int t = __shfl_up_sync(0xFFu, si, o);
            if (lane >= o) si += t;
        }
        wsum[lane] = si - s;
    }
    __syncthreads();
    int excl = incl - v + wsum[wid];
    if (i < TOT) g_off[i] = excl;
    if (threadIdx.x == 255) g_bsum[blockIdx.x] = excl + v;
}

__global__ void k_scan2(int nb) {
    __shared__ int wsum[16];
    const int TOT = 2 * NN;
    int t = threadIdx.x;
    int lane = t & 31;
    int wid = t >> 5;
    int v = (t < nb) ? g_bsum[t] : 0;
    int incl = v;
    #pragma unroll
    for (int o = 1; o < 32; o <<= 1) {
        int u = __shfl_up_sync(0xFFFFFFFFu, incl, o);
        if (lane >= o) incl += u;
    }
    if (lane == 31) wsum[wid] = incl;
    __syncthreads();
    if (wid == 0 && lane < 16) {
        int s = wsum[lane];
        int si = s;
        #pragma unroll
        for (int o = 1; o < 16; o <<= 1) {
            int u = __shfl_up_sync(0xFFFFu, si, o);
            if (lane >= o) si += u;
        }
        wsum[lane] = si - s;
    }
    __syncthreads();
    int excl = incl - v + wsum[wid];
    if (t < nb) g_bsum[t] = excl;
    if (t == nb - 1) g_off[TOT] = excl + v;
}

__global__ void k_scan3() {
    const int TOT = 2 * NN;
    int i = blockIdx.x * 256 + threadIdx.x;
    if (i < TOT) {
        int o = g_off[i] + g_bsum[blockIdx.x];
        g_off[i] = o;
        g_cur[i] = o;
    }
}

__global__ void k_fill(const int* __restrict__ ei, const int* __restrict__ et) {
    int e = blockIdx.x * blockDim.x + threadIdx.x;
    if (e >= EE) return;
    int s = ei[e];
    int d = ei[EE + e];
    int r = et[e];
    int pos = atomicAdd(&g_cur[r * NN + d], 1);
    g_elist[pos] = s;
}

// ---------------- gather (per-relation segment mean) ----------------
__global__ void k_gather(const float* __restrict__ h, float* __restrict__ mean) {
    int w = (blockIdx.x * blockDim.x + threadIdx.x) >> 5;
    int lane = threadIdx.x & 31;
    if (w >= 2 * NN) return;
    int beg = g_off[w], end = g_off[w + 1];
    float4 a0 = make_float4(0.f, 0.f, 0.f, 0.f);
    float4 a1 = a0;
    const bool tail = (lane < 8);
    #pragma unroll 2
    for (int k = beg; k < end; k++) {
        int s = g_elist[k];
        const float4* hp = reinterpret_cast<const float4*>(h + (size_t)s * HH);
        float4 v = __ldg(&hp[lane]);
        a0.x += v.x; a0.y += v.y; a0.z += v.z; a0.w += v.w;
        if (tail) {
            float4 u = __ldg(&hp[32 + lane]);
            a1.x += u.x; a1.y += u.y; a1.z += u.z; a1.w += u.w;
        }
    }
    int deg = end - beg;
    float inv = (deg > 0) ? 1.f / (float)deg : 0.f;
    a0.x *= inv; a0.y *= inv; a0.z *= inv; a0.w *= inv;
    float4* o = reinterpret_cast<float4*>(mean + (size_t)w * HH);
    o[lane] = a0;
    if (tail) {
        a1.x *= inv; a1.y *= inv; a1.z *= inv; a1.w *= inv;
        o[32 + lane] = a1;
    }
}

// packed RN bf16 hi/lo split of two floats: returns (hi_pair, lo_pair)
__device__ __forceinline__ void split2(float x0, float x1, uint32_t& hp, uint32_t& lp) {
    asm("cvt.rn.bf16x2.f32 %0, %1, %2;" : "=r"(hp) : "f"(x1), "f"(x0));
    float h0 = __uint_as_float(hp << 16);
    float h1 = __uint_as_float(hp & 0xFFFF0000u);
    float l0 = x0 - h0;
    float l1 = x1 - h1;
    asm("cvt.rn.bf16x2.f32 %0, %1, %2;" : "=r"(lp) : "f"(l1), "f"(l0));
}

// ---------------- WMMA bf16-split GEMM (single buffer, BM=128, BK templated) ----------------
// C[:, cbase:cbase+BN] = act( sum_t A_t[M,K] @ W_t[K,BN] + bias )
// A fp32 (RN bf16 hi/lo split2 in staging, STS.64); W from precomputed bf16 hi/lo planes.
template <int BK, int BN, bool RELU>
__global__ __launch_bounds__(256) void mm_gemm(
    const float* __restrict__ A0, const __nv_bfloat16* __restrict__ W0h, const __nv_bfloat16* __restrict__ W0l,
    const float* __restrict__ A1, const __nv_bfloat16* __restrict__ W1h, const __nv_bfloat16* __restrict__ W1l,
    const float* __restrict__ A2, const __nv_bfloat16* __restrict__ W2h, const __nv_bfloat16* __restrict__ W2l,
    const float* __restrict__ bias, float* __restrict__ C,
    int M, int K, int ldC, int cbase, int nterms)
{
    constexpr int BM = 128;
    constexpr int TN16 = BN / 16;
    constexpr int WN = (BN == 160) ? 2 : 1;   // warps along N
    constexpr int WM = 8 / WN;                // warps along M
    constexpr int MT = BM / (16 * WM);        // m16 tiles per warp
    constexpr int NT = TN16 / WN;             // n16 tiles per warp
    constexpr int LDA = BK + 8;
    constexpr int LDB = BN + 8;
    constexpr int QPR = BK / 4;               // quads per A row
    constexpr int KS = BK / 16;               // k16 steps per chunk

    extern __shared__ char sm[];
    __nv_bfloat16* sAh = reinterpret_cast<__nv_bfloat16*>(sm);
    __nv_bfloat16* sAl = sAh + BM * LDA;
    __nv_bfloat16* sBh = sAl + BM * LDA;
    __nv_bfloat16* sBl = sBh + BK * LDB;
    float* sstage = reinterpret_cast<float*>(sBl + BK * LDB);

    const int tid = threadIdx.x;
    const int wid = tid >> 5;
    const int lane = tid & 31;
    const int rowbase = blockIdx.x * BM;
    const int warp_m = wid % WM;
    const int warp_n = wid / WM;
    const int nbase = warp_n * NT * 16;

    wmma::fragment<wmma::accumulator, 16, 16, 16, float> acc[MT][NT];
    #pragma unroll
    for (int i = 0; i < MT; i++)
        #pragma unroll
        for (int j = 0; j < NT; j++) wmma::fill_fragment(acc[i][j], 0.f);

    const bool vec = (K % BK == 0);

    for (int term = 0; term < nterms; term++) {
        const float* A = (term == 0) ? A0 : (term == 1) ? A1 : A2;
        const __nv_bfloat16* Wh = (term == 0) ? W0h : (term == 1) ? W1h : W2h;
        const __nv_bfloat16* Wl = (term == 0) ? W0l : (term == 1) ? W1l : W2l;
        const int nck = (K + BK - 1) / BK;

        for (int ck = 0; ck < nck; ck++) {
            const int kt = ck * BK;
            // ---- stage A tile [BM x BK]: RN hi/lo split2, packed STS.64 ----
            if (vec) {
                #pragma unroll
                for (int p = 0; p < BM * QPR / 256; p++) {
                    int idx = tid + 256 * p;
                    int r = idx / QPR, kq = idx % QPR;
                    int gr = rowbase + r;
                    float4 v = make_float4(0.f, 0.f, 0.f, 0.f);
                    if (gr < M)
                        v = *reinterpret_cast<const float4*>(A + (size_t)gr * K + kt + kq * 4);
                    uint32_t h01, l01, h23, l23;
                    split2(v.x, v.y, h01, l01);
                    split2(v.z, v.w, h23, l23);
                    *reinterpret_cast<uint2*>(sAh + r * LDA + kq * 4) = make_uint2(h01, h23);
                    *reinterpret_cast<uint2*>(sAl + r * LDA + kq * 4) = make_uint2(l01, l23);
                }
            } else {
                for (int idx = tid; idx < BM * BK; idx += 256) {
                    int r = idx / BK, c = idx % BK;
                    int gr = rowbase + r, gk = kt + c;
                    float x = (gr < M && gk < K) ? A[(size_t)gr * K + gk] : 0.f;
                    __nv_bfloat16 hi = __float2bfloat16(x);
                    __nv_bfloat16 lo = __float2bfloat16(x - __bfloat162float(hi));
                    sAh[r * LDA + c] = hi;
                    sAl[r * LDA + c] = lo;
                }
            }
            // ---- stage W tile [BK x BN]: pure bf16 copy from planes ----
            {
                constexpr int ITER = BK * BN / 8;   // uint4 slots
                for (int idx = tid; idx < ITER; idx += 256) {
                    int r = idx / (BN / 8);
                    int c8 = (idx % (BN / 8)) * 8;
                    int gk = kt + r;
                    uint4 vh = make_uint4(0u, 0u, 0u, 0u);
                    uint4 vl = vh;
                    if (gk < K) {
                        vh = *reinterpret_cast<const uint4*>(Wh + (size_t)gk * BN + c8);
                        vl = *reinterpret_cast<const uint4*>(Wl + (size_t)gk * BN + c8);
                    }
                    *reinterpret_cast<uint4*>(sBh + r * LDB + c8) = vh;
                    *reinterpret_cast<uint4*>(sBl + r * LDB + c8) = vl;
                }
            }
            __syncthreads();

            // ---- KS k16 steps, 3-product split MMA (array b-frags, i-outer) ----
            #pragma unroll
            for (int ks = 0; ks < KS; ks++) {
                wmma::fragment<wmma::matrix_a, 16, 16, 16, __nv_bfloat16, wmma::row_major> ah[MT], al[MT];
                #pragma unroll
                for (int i = 0; i < MT; i++) {
                    int r0 = (warp_m * MT + i) * 16;
                    wmma::load_matrix_sync(ah[i], sAh + r0 * LDA + ks * 16, LDA);
                    wmma::load_matrix_sync(al[i], sAl + r0 * LDA + ks * 16, LDA);
                }
                wmma::fragment<wmma::matrix_b, 16, 16, 16, __nv_bfloat16, wmma::row_major> bh[NT], bl[NT];
                #pragma unroll
                for (int j = 0; j < NT; j++) {
                    wmma::load_matrix_sync(bh[j], sBh + ks * 16 * LDB + nbase + j * 16, LDB);
                    wmma::load_matrix_sync(bl[j], sBl + ks * 16 * LDB + nbase + j * 16, LDB);
                }
                #pragma unroll
                for (int i = 0; i < MT; i++)
                    #pragma unroll
                    for (int j = 0; j < NT; j++) {
                        wmma::mma_sync(acc[i][j], ah[i], bh[j], acc[i][j]);
                        wmma::mma_sync(acc[i][j], ah[i], bl[j], acc[i][j]);
                        wmma::mma_sync(acc[i][j], al[i], bh[j], acc[i][j]);
                    }
            }
            __syncthreads();
        }
    }

    // ---- epilogue: per-warp 16x16 stage -> bias + leaky + float4 stores ----
    float* st = sstage + wid * 256;
    #pragma unroll
    for (int i = 0; i < MT; i++) {
        #pragma unroll
        for (int j = 0; j < NT; j++) {
            wmma::store_matrix_sync(st, acc[i][j], 16, wmma::mem_row_major);
            __syncwarp();
            int r = lane >> 1;
            int c0 = (lane & 1) * 8;
            int grow = rowbase + (warp_m * MT + i) * 16 + r;
            if (grow < M) {
                int cloc = nbase + j * 16 + c0;
                float* cp = C + (size_t)grow * ldC + cbase + cloc;
                #pragma unroll
                for (int q = 0; q < 2; q++) {
                    float4 v;
                    v.x = st[r * 16 + c0 + q * 4 + 0] + bias[cloc + q * 4 + 0];
                    v.y = st[r * 16 + c0 + q * 4 + 1] + bias[cloc + q * 4 + 1];
                    v.z = st[r * 16 + c0 + q * 4 + 2] + bias[cloc + q * 4 + 2];
                    v.w = st[r * 16 + c0 + q * 4 + 3] + bias[cloc + q * 4 + 3];
                    if (RELU) {
                        v.x = (v.x >= 0.f) ? v.x : LEAK * v.x;
                        v.y = (v.y >= 0.f) ? v.y : LEAK * v.y;
                        v.z = (v.z >= 0.f) ? v.z : LEAK * v.z;
                        v.w = (v.w >= 0.f) ? v.w : LEAK * v.w;
                    }
                    *reinterpret_cast<float4*>(cp + q * 4) = v;
                }
            }
            __syncwarp();
        }
    }
}

// ---------------- final tiny head: out = em @ W_o2 + b_o2 ----------------
__global__ void k_out2(const float* __restrict__ em, const float* __restrict__ W2,
                       const float* __restrict__ b2, float* __restrict__ out) {
    __shared__ float es[64 * 80];
    int nb = blockIdx.x * 64;
    for (int idx = threadIdx.x; idx < 64 * 80; idx += 256) {
        int n = nb + idx / 80;
        es[idx] = (n < NN) ? em[(size_t)n * 80 + idx % 80] : 0.f;
    }
    __syncthreads();
    int t = threadIdx.x;
    if (t < 128) {
        int ln = t >> 1;
        int c = t & 1;
        int n = nb + ln;
        if (n < NN) {
            float s = b2[c];
            #pragma unroll 8
            for (int k = 0; k < 80; k++) s += es[ln * 80 + k] * W2[k * 2 + c];
            out[(size_t)n * 2 + c] = s;
        }
    }
}

// smem bytes for mm_gemm<BK,BN,...> (single buffer, BM=128)
static int smem_bytes(int BK, int BN) {
    return 2 * (128 * (BK + 8)) * 2 + 2 * (BK * (BN + 8)) * 2 + 8 * 256 * 4;
}

// ---------------- launch ----------------
extern "C" void kernel_launch(void* const* d_in, const int* in_sizes, int n_in,
                              void* d_out, int out_size) {
    const float* pre_x   = (const float*)d_in[0];
    const int*   ei      = (const int*)d_in[2];
    const int*   et      = (const int*)d_in[3];
    const float* numprop = (const float*)d_in[4];
    const float* numcat  = (const float*)d_in[5];
    const float* des     = (const float*)d_in[6];
    const float* tweet   = (const float*)d_in[7];
    const float* W_np = (const float*)d_in[8],  *b_np = (const float*)d_in[9];
    const float* W_nc = (const float*)d_in[10], *b_nc = (const float*)d_in[11];
    const float* W_des = (const float*)d_in[12], *b_des = (const float*)d_in[13];
    const float* W_text = (const float*)d_in[14], *b_text = (const float*)d_in[15];
    const float* W_tweet = (const float*)d_in[16], *b_tweet = (const float*)d_in[17];
    const float* W_in = (const float*)d_in[18], *b_in = (const float*)d_in[19];
    const float* W_rel1 = (const float*)d_in[20];
    const float* W_root1 = (const float*)d_in[21], *b_conv1 = (const float*)d_in[22];
    const float* W_rel2 = (const float*)d_in[23];
    const float* W_root2 = (const float*)d_in[24], *b_conv2 = (const float*)d_in[25];
    const float* W_o1 = (const float*)d_in[26], *b_o1 = (const float*)d_in[27];
    const float* W_o2 = (const float*)d_in[28], *b_o2 = (const float*)d_in[29];

    float* t;    cudaGetSymbolAddress((void**)&t, g_t);
    float* hA;   cudaGetSymbolAddress((void**)&hA, g_hA);
    float* hB;   cudaGetSymbolAddress((void**)&hB, g_hB);
    float* mean; cudaGetSymbolAddress((void**)&mean, g_mean);
    __nv_bfloat16* wh; cudaGetSymbolAddress((void**)&wh, g_wh);
    __nv_bfloat16* wl; cudaGetSymbolAddress((void**)&wl, g_wl);

    float* out = (float*)d_out;            // [N,2]
    float* em = out + 2 * (size_t)NN;      // [N,80]

    const int SM_E  = smem_bytes(64, 32);    // 55296 (encoders, BK=64)
    const int SM160 = smem_bytes(32, 160);   // 50176
    const int SM80  = smem_bytes(32, 80);    // 39936
    cudaFuncSetAttribute(mm_gemm<64, 32, true>,    cudaFuncAttributeMaxDynamicSharedMemorySize, SM_E);
    cudaFuncSetAttribute(mm_gemm<32, 160, true>,   cudaFuncAttributeMaxDynamicSharedMemorySize, SM160);
    cudaFuncSetAttribute(mm_gemm<32, 160, false>,  cudaFuncAttributeMaxDynamicSharedMemorySize, SM160);
    cudaFuncSetAttribute(mm_gemm<32, 80, true>,    cudaFuncAttributeMaxDynamicSharedMemorySize, SM80);

    // ---- weight split precompute (launch 0) ----
    WSegs ws;
    const float* srcs[13] = {W_np, W_nc, W_des, W_text, W_tweet, W_in,
                             W_root1, W_rel1, W_rel1 + HH * HH,
                             W_root2, W_rel2, W_rel2 + HH * HH, W_o1};
    const int lens[13] = {192, 352, 24576, 24576, 24576, 25600,
                          25600, 25600, 25600, 25600, 25600, 25600, 12800};
    const int offs[13] = {OFF_NP, OFF_NC, OFF_DES, OFF_TEXT, OFF_TW, OFF_IN,
                          OFF_ROOT1, OFF_REL1A, OFF_REL1B,
                          OFF_ROOT2, OFF_REL2A, OFF_REL2B, OFF_O1};
    for (int i = 0; i < 13; i++) { ws.src[i] = srcs[i]; ws.len[i] = lens[i]; ws.off[i] = offs[i]; }
    k_splitw<<<(W_TOTAL + 255) / 256, 256>>>(ws);

    dim3 gM((NN + 127) / 128);   // 391

    // ---- encoder GEMMs first (launches 1-5; ncu -s 5 captures pre_x K=768 GEMM) ----
    // concat layout: np | nc | des | tweet@W_text | pre_x@W_tweet
    mm_gemm<64, 32, true><<<gM, 256, SM_E>>>(
        numprop, wh + OFF_NP, wl + OFF_NP, nullptr, nullptr, nullptr,
        nullptr, nullptr, nullptr, b_np, t, NN, 6, HH, 0, 1);
    mm_gemm<64, 32, true><<<gM, 256, SM_E>>>(
        numcat, wh + OFF_NC, wl + OFF_NC, nullptr, nullptr, nullptr,
        nullptr, nullptr, nullptr, b_nc, t, NN, 11, HH, 32, 1);
    mm_gemm<64, 32, true><<<gM, 256, SM_E>>>(
        des, wh + OFF_DES, wl + OFF_DES, nullptr, nullptr, nullptr,
        nullptr, nullptr, nullptr, b_des, t, NN, 768, HH, 64, 1);
    mm_gemm<64, 32, true><<<gM, 256, SM_E>>>(
        tweet, wh + OFF_TEXT, wl + OFF_TEXT, nullptr, nullptr, nullptr,
        nullptr, nullptr, nullptr, b_text, t, NN, 768, HH, 96, 1);
    mm_gemm<64, 32, true><<<gM, 256, SM_E>>>(
        pre_x, wh + OFF_TW, wl + OFF_TW, nullptr, nullptr, nullptr,
        nullptr, nullptr, nullptr, b_tweet, t, NN, 768, HH, 128, 1);

    // h = leaky(t @ W_in + b_in)
    mm_gemm<32, 160, true><<<gM, 256, SM160>>>(
        t, wh + OFF_IN, wl + OFF_IN, nullptr, nullptr, nullptr,
        nullptr, nullptr, nullptr, b_in, hA, NN, HH, HH, 0, 1);

    // ---- CSR build (needed only before the first gather) ----
    const int NB = (2 * NN + 255) / 256;   // 391
    k_zero_deg<<<NB, 256>>>();
    k_count<<<(EE + 255) / 256, 256>>>(ei, et);
    k_scan1<<<NB, 256>>>();
    k_scan2<<<1, 512>>>(NB);
    k_scan3<<<NB, 256>>>();
    k_fill<<<(EE + 255) / 256, 256>>>(ei, et);

    // conv1
    k_gather<<<(2 * NN * 32 + 255) / 256, 256>>>(hA, mean);
    mm_gemm<32, 160, false><<<gM, 256, SM160>>>(
        hA, wh + OFF_ROOT1, wl + OFF_ROOT1,
        mean, wh + OFF_REL1A, wl + OFF_REL1A,
        mean + (size_t)NN * HH, wh + OFF_REL1B, wl + OFF_REL1B,
        b_conv1, hB, NN, HH, HH, 0, 3);

    // conv2
    k_gather<<<(2 * NN * 32 + 255) / 256, 256>>>(hB, mean);
    mm_gemm<32, 160, false><<<gM, 256, SM160>>>(
        hB, wh + OFF_ROOT2, wl + OFF_ROOT2,
        mean, wh + OFF_REL2A, wl + OFF_REL2A,
        mean + (size_t)NN * HH, wh + OFF_REL2B, wl + OFF_REL2B,
        b_conv2, hA, NN, HH, HH, 0, 3);

    // em = leaky(h @ W_o1 + b_o1)
    mm_gemm<32, 80, true><<<gM, 256, SM80>>>(
        hA, wh + OFF_O1, wl + OFF_O1, nullptr, nullptr, nullptr,
        nullptr, nullptr, nullptr, b_o1, em, NN, HH, 80, 0, 1);

    // out = em @ W_o2 + b_o2
    k_out2<<<(NN + 63) / 64, 256>>>(em, W_o2, b_o2, out);
}

// round 17
// speedup vs baseline: 1.5454x; 1.5454x over previous
#include <cuda_runtime.h>
#include <cuda_bf16.h>
#include <mma.h>
#include <cstdint>

using namespace nvcuda;

// Problem constants
static constexpr int NN = 50000;   // nodes
static constexpr int EE = 800000;  // edges
static constexpr int HH = 160;     // hidden
static constexpr float LEAK = 0.01f;

// ---------------- device scratch (allocation-free rule) ----------------
__device__ float g_t[NN * HH];          // encoder concat output
__device__ float g_hA[NN * HH];
__device__ float g_hB[NN * HH];
__device__ float g_mean[2 * NN * HH];   // per-relation aggregated means
__device__ int   g_deg[2 * NN];
__device__ int   g_off[2 * NN + 1];
__device__ int   g_cur[2 * NN];
__device__ int   g_elist[EE];
__device__ int   g_bsum[512];

// Weight split planes (bf16 hi / lo), precomputed once per replay.
static constexpr int OFF_NP    = 0;              // 6*32
static constexpr int OFF_NC    = 192;            // 11*32
static constexpr int OFF_DES   = 544;            // 768*32
static constexpr int OFF_TEXT  = 25120;
static constexpr int OFF_TW    = 49696;
static constexpr int OFF_IN    = 74272;          // 160*160
static constexpr int OFF_ROOT1 = 99872;
static constexpr int OFF_REL1A = 125472;
static constexpr int OFF_REL1B = 151072;
static constexpr int OFF_ROOT2 = 176672;
static constexpr int OFF_REL2A = 202272;
static constexpr int OFF_REL2B = 227872;
static constexpr int OFF_O1    = 253472;         // 160*80
static constexpr int W_TOTAL   = 266272;
__device__ __align__(16) __nv_bfloat16 g_wh[W_TOTAL];
__device__ __align__(16) __nv_bfloat16 g_wl[W_TOTAL];

// ---------------- weight split precompute ----------------
struct WSegs {
    const float* src[13];
    int len[13];
    int off[13];
};
__global__ void k_splitw(WSegs s) {
    int i = blockIdx.x * blockDim.x + threadIdx.x;
    #pragma unroll
    for (int seg = 0; seg < 13; seg++) {
        int l = s.len[seg];
        if (i < l) {
            float x = s.src[seg][i];
            __nv_bfloat16 hb = __float2bfloat16(x);
            g_wh[s.off[seg] + i] = hb;
            g_wl[s.off[seg] + i] = __float2bfloat16(x - __bfloat162float(hb));
            return;
        }
        i -= l;
    }
}

// ---------------- CSR build ----------------
__global__ void k_zero_deg() {
    int i = blockIdx.x * blockDim.x + threadIdx.x;
    if (i < 2 * NN) g_deg[i] = 0;
}

__global__ void k_count(const int* __restrict__ ei, const int* __restrict__ et) {
    int e = blockIdx.x * blockDim.x + threadIdx.x;
    if (e >= EE) return;
    int d = ei[EE + e];
    int r = et[e];
    atomicAdd(&g_deg[r * NN + d], 1);
}

// ---- decoupled 3-phase scan over 2N counts ----
__global__ void k_scan1() {
    __shared__ int wsum[8];
    const int TOT = 2 * NN;
    int i = blockIdx.x * 256 + threadIdx.x;
    int lane = threadIdx.x & 31;
    int wid = threadIdx.x >> 5;
    int v = (i < TOT) ? g_deg[i] : 0;
    int incl = v;
    #pragma unroll
    for (int o = 1; o < 32; o <<= 1) {
        int t = __shfl_up_sync(0xFFFFFFFFu, incl, o);
        if (lane >= o) incl += t;
    }
    if (lane == 31) wsum[wid] = incl;
    __syncthreads();
    if (wid == 0 && lane < 8) {
        int s = wsum[lane];
        int si = s;
        #pragma unroll
        for (int o = 1; o < 8; o <<= 1) {
            int t = __shfl_up_sync(0xFFu, si, o);
            if (lane >= o) si += t;
        }
        wsum[lane] = si - s;
    }
    __syncthreads();
    int excl = incl - v + wsum[wid];
    if (i < TOT) g_off[i] = excl;
    if (threadIdx.x == 255) g_bsum[blockIdx.x] = excl + v;
}

__global__ void k_scan2(int nb) {
    __shared__ int wsum[16];
    const int TOT = 2 * NN;
    int t = threadIdx.x;
    int lane = t & 31;
    int wid = t >> 5;
    int v = (t < nb) ? g_bsum[t] : 0;
    int incl = v;
    #pragma unroll
    for (int o = 1; o < 32; o <<= 1) {
        int u = __shfl_up_sync(0xFFFFFFFFu, incl, o);
        if (lane >= o) incl += u;
    }
    if (lane == 31) wsum[wid] = incl;
    __syncthreads();
    if (wid == 0 && lane < 16) {
        int s = wsum[lane];
        int si = s;
        #pragma unroll
        for (int o = 1; o < 16; o <<= 1) {
            int u = __shfl_up_sync(0xFFFFu, si, o);
            if (lane >= o) si += u;
        }
        wsum[lane] = si - s;
    }
    __syncthreads();
    int excl = incl - v + wsum[wid];
    if (t < nb) g_bsum[t] = excl;
    if (t == nb - 1) g_off[TOT] = excl + v;
}

__global__ void k_scan3() {
    const int TOT = 2 * NN;
    int i = blockIdx.x * 256 + threadIdx.x;
    if (i < TOT) {
        int o = g_off[i] + g_bsum[blockIdx.x];
        g_off[i] = o;
        g_cur[i] = o;
    }
}

__global__ void k_fill(const int* __restrict__ ei, const int* __restrict__ et) {
    int e = blockIdx.x * blockDim.x + threadIdx.x;
    if (e >= EE) return;
    int s = ei[e];
    int d = ei[EE + e];
    int r = et[e];
    int pos = atomicAdd(&g_cur[r * NN + d], 1);
    g_elist[pos] = s;
}

// ---------------- gather (per-relation segment mean) ----------------
__global__ void k_gather(const float* __restrict__ h, float* __restrict__ mean) {
    int w = (blockIdx.x * blockDim.x + threadIdx.x) >> 5;
    int lane = threadIdx.x & 31;
    if (w >= 2 * NN) return;
    int beg = g_off[w], end = g_off[w + 1];
    float4 a0 = make_float4(0.f, 0.f, 0.f, 0.f);
    float4 a1 = a0;
    const bool tail = (lane < 8);
    #pragma unroll 2
    for (int k = beg; k < end; k++) {
        int s = g_elist[k];
        const float4* hp = reinterpret_cast<const float4*>(h + (size_t)s * HH);
        float4 v = __ldg(&hp[lane]);
        a0.x += v.x; a0.y += v.y; a0.z += v.z; a0.w += v.w;
        if (tail) {
            float4 u = __ldg(&hp[32 + lane]);
            a1.x += u.x; a1.y += u.y; a1.z += u.z; a1.w += u.w;
        }
    }
    int deg = end - beg;
    float inv = (deg > 0) ? 1.f / (float)deg : 0.f;
    a0.x *= inv; a0.y *= inv; a0.z *= inv; a0.w *= inv;
    float4* o = reinterpret_cast<float4*>(mean + (size_t)w * HH);
    o[lane] = a0;
    if (tail) {
        a1.x *= inv; a1.y *= inv; a1.z *= inv; a1.w *= inv;
        o[32 + lane] = a1;
    }
}

// packed RN bf16 hi/lo split of two floats: returns (hi_pair, lo_pair)
__device__ __forceinline__ void split2(float x0, float x1, uint32_t& hp, uint32_t& lp) {
    asm("cvt.rn.bf16x2.f32 %0, %1, %2;" : "=r"(hp) : "f"(x1), "f"(x0));
    float h0 = __uint_as_float(hp << 16);
    float h1 = __uint_as_float(hp & 0xFFFF0000u);
    float l0 = x0 - h0;
    float l1 = x1 - h1;
    asm("cvt.rn.bf16x2.f32 %0, %1, %2;" : "=r"(lp) : "f"(l1), "f"(l0));
}

// ---------------- WMMA bf16-split GEMM (R13 config + split2 staging) ----------------
// BM=128, BK=32, single buffer, array B-frags, i-outer MMA loop.
// C[:, cbase:cbase+BN] = act( sum_t A_t[M,K] @ W_t[K,BN] + bias )
template <int BN, bool RELU>
__global__ __launch_bounds__(256) void mm_gemm(
    const float* __restrict__ A0, const __nv_bfloat16* __restrict__ W0h, const __nv_bfloat16* __restrict__ W0l,
    const float* __restrict__ A1, const __nv_bfloat16* __restrict__ W1h, const __nv_bfloat16* __restrict__ W1l,
    const float* __restrict__ A2, const __nv_bfloat16* __restrict__ W2h, const __nv_bfloat16* __restrict__ W2l,
    const float* __restrict__ bias, float* __restrict__ C,
    int M, int K, int ldC, int cbase, int nterms)
{
    constexpr int BM = 128;
    constexpr int TN16 = BN / 16;
    constexpr int WN = (BN == 160) ? 2 : 1;   // warps along N
    constexpr int WM = 8 / WN;                // warps along M
    constexpr int MT = BM / (16 * WM);        // m16 tiles per warp
    constexpr int NT = TN16 / WN;             // n16 tiles per warp
    constexpr int LDA = 40;                   // 32 + 8 pad (bf16)
    constexpr int LDB = BN + 8;

    extern __shared__ char sm[];
    __nv_bfloat16* sAh = reinterpret_cast<__nv_bfloat16*>(sm);
    __nv_bfloat16* sAl = sAh + BM * LDA;
    __nv_bfloat16* sBh = sAl + BM * LDA;
    __nv_bfloat16* sBl = sBh + 32 * LDB;
    float* sstage = reinterpret_cast<float*>(sBl + 32 * LDB);

    const int tid = threadIdx.x;
    const int wid = tid >> 5;
    const int lane = tid & 31;
    const int rowbase = blockIdx.x * BM;
    const int warp_m = wid % WM;
    const int warp_n = wid / WM;
    const int nbase = warp_n * NT * 16;

    wmma::fragment<wmma::accumulator, 16, 16, 16, float> acc[MT][NT];
    #pragma unroll
    for (int i = 0; i < MT; i++)
        #pragma unroll
        for (int j = 0; j < NT; j++) wmma::fill_fragment(acc[i][j], 0.f);

    const bool vec = (K % 32 == 0);

    for (int term = 0; term < nterms; term++) {
        const float* A = (term == 0) ? A0 : (term == 1) ? A1 : A2;
        const __nv_bfloat16* Wh = (term == 0) ? W0h : (term == 1) ? W1h : W2h;
        const __nv_bfloat16* Wl = (term == 0) ? W0l : (term == 1) ? W1l : W2l;
        const int nck = (K + 31) >> 5;

        for (int ck = 0; ck < nck; ck++) {
            const int kt = ck * 32;
            // ---- stage A tile [128 x 32]: RN hi/lo split2, packed STS.64 ----
            if (vec) {
                #pragma unroll
                for (int p = 0; p < 4; p++) {
                    int idx = tid + 256 * p;       // 1024 quads
                    int r = idx >> 3, kq = idx & 7;
                    int gr = rowbase + r;
                    float4 v = make_float4(0.f, 0.f, 0.f, 0.f);
                    if (gr < M)
                        v = *reinterpret_cast<const float4*>(A + (size_t)gr * K + kt + kq * 4);
                    uint32_t h01, l01, h23, l23;
                    split2(v.x, v.y, h01, l01);
                    split2(v.z, v.w, h23, l23);
                    *reinterpret_cast<uint2*>(sAh + r * LDA + kq * 4) = make_uint2(h01, h23);
                    *reinterpret_cast<uint2*>(sAl + r * LDA + kq * 4) = make_uint2(l01, l23);
                }
            } else {
                for (int idx = tid; idx < BM * 32; idx += 256) {
                    int r = idx >> 5, c = idx & 31;
                    int gr = rowbase + r, gk = kt + c;
                    float x = (gr < M && gk < K) ? A[(size_t)gr * K + gk] : 0.f;
                    __nv_bfloat16 hi = __float2bfloat16(x);
                    __nv_bfloat16 lo = __float2bfloat16(x - __bfloat162float(hi));
                    sAh[r * LDA + c] = hi;
                    sAl[r * LDA + c] = lo;
                }
            }
            // ---- stage W tile [32 x BN]: pure bf16 copy from planes ----
            {
                constexpr int ITER = 4 * BN;       // 32*BN/8 uint4 slots
                for (int idx = tid; idx < ITER; idx += 256) {
                    int r = idx / (BN / 8);
                    int c8 = (idx % (BN / 8)) * 8;
                    int gk = kt + r;
                    uint4 vh = make_uint4(0u, 0u, 0u, 0u);
                    uint4 vl = vh;
                    if (gk < K) {
                        vh = *reinterpret_cast<const uint4*>(Wh + (size_t)gk * BN + c8);
                        vl = *reinterpret_cast<const uint4*>(Wl + (size_t)gk * BN + c8);
                    }
                    *reinterpret_cast<uint4*>(sBh + r * LDB + c8) = vh;
                    *reinterpret_cast<uint4*>(sBl + r * LDB + c8) = vl;
                }
            }
            __syncthreads();

            // ---- 2 k16 steps, 3-product split MMA (array b-frags, i-outer) ----
            #pragma unroll
            for (int ks = 0; ks < 2; ks++) {
                wmma::fragment<wmma::matrix_a, 16, 16, 16, __nv_bfloat16, wmma::row_major> ah[MT], al[MT];
                #pragma unroll
                for (int i = 0; i < MT; i++) {
                    int r0 = (warp_m * MT + i) * 16;
                    wmma::load_matrix_sync(ah[i], sAh + r0 * LDA + ks * 16, LDA);
                    wmma::load_matrix_sync(al[i], sAl + r0 * LDA + ks * 16, LDA);
                }
                wmma::fragment<wmma::matrix_b, 16, 16, 16, __nv_bfloat16, wmma::row_major> bh[NT], bl[NT];
                #pragma unroll
                for (int j = 0; j < NT; j++) {
                    wmma::load_matrix_sync(bh[j], sBh + ks * 16 * LDB + nbase + j * 16, LDB);
                    wmma::load_matrix_sync(bl[j], sBl + ks * 16 * LDB + nbase + j * 16, LDB);
                }
                #pragma unroll
                for (int i = 0; i < MT; i++)
                    #pragma unroll
                    for (int j = 0; j < NT; j++) {
                        wmma::mma_sync(acc[i][j], ah[i], bh[j], acc[i][j]);
                        wmma::mma_sync(acc[i][j], ah[i], bl[j], acc[i][j]);
                        wmma::mma_sync(acc[i][j], al[i], bh[j], acc[i][j]);
                    }
            }
            __syncthreads();
        }
    }

    // ---- epilogue: per-warp 16x16 stage -> bias + leaky + float4 stores ----
    float* st = sstage + wid * 256;
    #pragma unroll
    for (int i = 0; i < MT; i++) {
        #pragma unroll
        for (int j = 0; j < NT; j++) {
            wmma::store_matrix_sync(st, acc[i][j], 16, wmma::mem_row_major);
            __syncwarp();
            int r = lane >> 1;
            int c0 = (lane & 1) * 8;
            int grow = rowbase + (warp_m * MT + i) * 16 + r;
            if (grow < M) {
                int cloc = nbase + j * 16 + c0;
                float* cp = C + (size_t)grow * ldC + cbase + cloc;
                #pragma unroll
                for (int q = 0; q < 2; q++) {
                    float4 v;
                    v.x = st[r * 16 + c0 + q * 4 + 0] + bias[cloc + q * 4 + 0];
                    v.y = st[r * 16 + c0 + q * 4 + 1] + bias[cloc + q * 4 + 1];
                    v.z = st[r * 16 + c0 + q * 4 + 2] + bias[cloc + q * 4 + 2];
                    v.w = st[r * 16 + c0 + q * 4 + 3] + bias[cloc + q * 4 + 3];
                    if (RELU) {
                        v.x = (v.x >= 0.f) ? v.x : LEAK * v.x;
                        v.y = (v.y >= 0.f) ? v.y : LEAK * v.y;
                        v.z = (v.z >= 0.f) ? v.z : LEAK * v.z;
                        v.w = (v.w >= 0.f) ? v.w : LEAK * v.w;
                    }
                    *reinterpret_cast<float4*>(cp + q * 4) = v;
                }
            }
            __syncwarp();
        }
    }
}

// ---------------- final tiny head: out = em @ W_o2 + b_o2 ----------------
__global__ void k_out2(const float* __restrict__ em, const float* __restrict__ W2,
                       const float* __restrict__ b2, float* __restrict__ out) {
    __shared__ float es[64 * 80];
    int nb = blockIdx.x * 64;
    for (int idx = threadIdx.x; idx < 64 * 80; idx += 256) {
        int n = nb + idx / 80;
        es[idx] = (n < NN) ? em[(size_t)n * 80 + idx % 80] : 0.f;
    }
    __syncthreads();
    int t = threadIdx.x;
    if (t < 128) {
        int ln = t >> 1;
        int c = t & 1;
        int n = nb + ln;
        if (n < NN) {
            float s = b2[c];
            #pragma unroll 8
            for (int k = 0; k < 80; k++) s += es[ln * 80 + k] * W2[k * 2 + c];
            out[(size_t)n * 2 + c] = s;
        }
    }
}

// smem bytes for mm_gemm<BN,...> (single buffer, BM=128, BK=32)
static int smem_bytes(int BN) {
    int LDB = BN + 8;
    return 2 * (128 * 40) * 2 + 2 * (32 * LDB) * 2 + 8 * 256 * 4;
}

// ---------------- launch ----------------
extern "C" void kernel_launch(void* const* d_in, const int* in_sizes, int n_in,
                              void* d_out, int out_size) {
    const float* pre_x   = (const float*)d_in[0];
    const int*   ei      = (const int*)d_in[2];
    const int*   et      = (const int*)d_in[3];
    const float* numprop = (const float*)d_in[4];
    const float* numcat  = (const float*)d_in[5];
    const float* des     = (const float*)d_in[6];
    const float* tweet   = (const float*)d_in[7];
    const float* W_np = (const float*)d_in[8],  *b_np = (const float*)d_in[9];
    const float* W_nc = (const float*)d_in[10], *b_nc = (const float*)d_in[11];
    const float* W_des = (const float*)d_in[12], *b_des = (const float*)d_in[13];
    const float* W_text = (const float*)d_in[14], *b_text = (const float*)d_in[15];
    const float* W_tweet = (const float*)d_in[16], *b_tweet = (const float*)d_in[17];
    const float* W_in = (const float*)d_in[18], *b_in = (const float*)d_in[19];
    const float* W_rel1 = (const float*)d_in[20];
    const float* W_root1 = (const float*)d_in[21], *b_conv1 = (const float*)d_in[22];
    const float* W_rel2 = (const float*)d_in[23];
    const float* W_root2 = (const float*)d_in[24], *b_conv2 = (const float*)d_in[25];
    const float* W_o1 = (const float*)d_in[26], *b_o1 = (const float*)d_in[27];
    const float* W_o2 = (const float*)d_in[28], *b_o2 = (const float*)d_in[29];

    float* t;    cudaGetSymbolAddress((void**)&t, g_t);
    float* hA;   cudaGetSymbolAddress((void**)&hA, g_hA);
    float* hB;   cudaGetSymbolAddress((void**)&hB, g_hB);
    float* mean; cudaGetSymbolAddress((void**)&mean, g_mean);
    __nv_bfloat16* wh; cudaGetSymbolAddress((void**)&wh, g_wh);
    __nv_bfloat16* wl; cudaGetSymbolAddress((void**)&wl, g_wl);

    float* out = (float*)d_out;            // [N,2]
    float* em = out + 2 * (size_t)NN;      // [N,80]

    const int SM160 = smem_bytes(160);     // 50176
    const int SM80  = smem_bytes(80);      // 39936
    const int SM32  = smem_bytes(32);      // 33792
    cudaFuncSetAttribute(mm_gemm<32, true>,   cudaFuncAttributeMaxDynamicSharedMemorySize, SM32);
    cudaFuncSetAttribute(mm_gemm<160, true>,  cudaFuncAttributeMaxDynamicSharedMemorySize, SM160);
    cudaFuncSetAttribute(mm_gemm<160, false>, cudaFuncAttributeMaxDynamicSharedMemorySize, SM160);
    cudaFuncSetAttribute(mm_gemm<80, true>,   cudaFuncAttributeMaxDynamicSharedMemorySize, SM80);

    // ---- weight split precompute (launch 0) ----
    WSegs ws;
    const float* srcs[13] = {W_np, W_nc, W_des, W_text, W_tweet, W_in,
                             W_root1, W_rel1, W_rel1 + HH * HH,
                             W_root2, W_rel2, W_rel2 + HH * HH, W_o1};
    const int lens[13] = {192, 352, 24576, 24576, 24576, 25600,
                          25600, 25600, 25600, 25600, 25600, 25600, 12800};
    const int offs[13] = {OFF_NP, OFF_NC, OFF_DES, OFF_TEXT, OFF_TW, OFF_IN,
                          OFF_ROOT1, OFF_REL1A, OFF_REL1B,
                          OFF_ROOT2, OFF_REL2A, OFF_REL2B, OFF_O1};
    for (int i = 0; i < 13; i++) { ws.src[i] = srcs[i]; ws.len[i] = lens[i]; ws.off[i] = offs[i]; }
    k_splitw<<<(W_TOTAL + 255) / 256, 256>>>(ws);

    dim3 gM((NN + 127) / 128);   // 391

    // ---- encoder GEMMs first (launches 1-5; ncu -s 5 captures pre_x K=768 GEMM) ----
    // concat layout: np | nc | des | tweet@W_text | pre_x@W_tweet
    mm_gemm<32, true><<<gM, 256, SM32>>>(
        numprop, wh + OFF_NP, wl + OFF_NP, nullptr, nullptr, nullptr,
        nullptr, nullptr, nullptr, b_np, t, NN, 6, HH, 0, 1);
    mm_gemm<32, true><<<gM, 256, SM32>>>(
        numcat, wh + OFF_NC, wl + OFF_NC, nullptr, nullptr, nullptr,
        nullptr, nullptr, nullptr, b_nc, t, NN, 11, HH, 32, 1);
    mm_gemm<32, true><<<gM, 256, SM32>>>(
        des, wh + OFF_DES, wl + OFF_DES, nullptr, nullptr, nullptr,
        nullptr, nullptr, nullptr, b_des, t, NN, 768, HH, 64, 1);
    mm_gemm<32, true><<<gM, 256, SM32>>>(
        tweet, wh + OFF_TEXT, wl + OFF_TEXT, nullptr, nullptr, nullptr,
        nullptr, nullptr, nullptr, b_text, t, NN, 768, HH, 96, 1);
    mm_gemm<32, true><<<gM, 256, SM32>>>(
        pre_x, wh + OFF_TW, wl + OFF_TW, nullptr, nullptr, nullptr,
        nullptr, nullptr, nullptr, b_tweet, t, NN, 768, HH, 128, 1);

    // h = leaky(t @ W_in + b_in)
    mm_gemm<160, true><<<gM, 256, SM160>>>(
        t, wh + OFF_IN, wl + OFF_IN, nullptr, nullptr, nullptr,
        nullptr, nullptr, nullptr, b_in, hA, NN, HH, HH, 0, 1);

    // ---- CSR build (needed only before the first gather) ----
    const int NB = (2 * NN + 255) / 256;   // 391
    k_zero_deg<<<NB, 256>>>();
    k_count<<<(EE + 255) / 256, 256>>>(ei, et);
    k_scan1<<<NB, 256>>>();
    k_scan2<<<1, 512>>>(NB);
    k_scan3<<<NB, 256>>>();
    k_fill<<<(EE + 255) / 256, 256>>>(ei, et);

    // conv1
    k_gather<<<(2 * NN * 32 + 255) / 256, 256>>>(hA, mean);
    mm_gemm<160, false><<<gM, 256, SM160>>>(
        hA, wh + OFF_ROOT1, wl + OFF_ROOT1,
        mean, wh + OFF_REL1A, wl + OFF_REL1A,
        mean + (size_t)NN * HH, wh + OFF_REL1B, wl + OFF_REL1B,
        b_conv1, hB, NN, HH, HH, 0, 3);

    // conv2
    k_gather<<<(2 * NN * 32 + 255) / 256, 256>>>(hB, mean);
    mm_gemm<160, false><<<gM, 256, SM160>>>(
        hB, wh + OFF_ROOT2, wl + OFF_ROOT2,
        mean, wh + OFF_REL2A, wl + OFF_REL2A,
        mean + (size_t)NN * HH, wh + OFF_REL2B, wl + OFF_REL2B,
        b_conv2, hA, NN, HH, HH, 0, 3);

    // em = leaky(h @ W_o1 + b_o1)
    mm_gemm<80, true><<<gM, 256, SM80>>>(
        hA, wh + OFF_O1, wl + OFF_O1, nullptr, nullptr, nullptr,
        nullptr, nullptr, nullptr, b_o1, em, NN, HH, 80, 0, 1);

    // out = em @ W_o2 + b_o2
    k_out2<<<(NN + 63) / 64, 256>>>(em, W_o2, b_o2, out);
}